// round 3
// baseline (speedup 1.0000x reference)
#include <cuda_runtime.h>
#include <cstdint>

// Problem constants
#define MTOK   8192          // B_*S = 4*2048 tokens
#define D      4096          // d_in = d_out
#define NADAPT 8
#define RANK   16
#define NR     128           // NADAPT*RANK, concatenated lora rank
#define LSCALE 2.0f          // ALPHA/RANK = 32/16

// Scratch: H[m][nr] = coef_n * (x @ A_all^T), 8192*128 fp32 = 4MB (static, allowed)
__device__ float g_H[MTOK * NR];

// ---------------------------------------------------------------------------
// PTX helpers
// ---------------------------------------------------------------------------
__device__ __forceinline__ void cp_async16(void* smem, const void* gmem) {
    uint32_t sa = (uint32_t)__cvta_generic_to_shared(smem);
    asm volatile("cp.async.cg.shared.global [%0], [%1], 16;\n" :: "r"(sa), "l"(gmem));
}
__device__ __forceinline__ void cp_commit() { asm volatile("cp.async.commit_group;\n"); }
__device__ __forceinline__ void cp_wait0()  { asm volatile("cp.async.wait_group 0;\n"); }

__device__ __forceinline__ uint32_t f2tf32(float f) {
    uint32_t r;
    asm("cvt.rna.tf32.f32 %0, %1;\n" : "=r"(r) : "f"(f));
    return r;
}

__device__ __forceinline__ void mma_tf32(float c[4],
                                         uint32_t a0, uint32_t a1, uint32_t a2, uint32_t a3,
                                         uint32_t b0, uint32_t b1) {
    asm volatile(
        "mma.sync.aligned.m16n8k8.row.col.f32.tf32.tf32.f32 "
        "{%0,%1,%2,%3}, {%4,%5,%6,%7}, {%8,%9}, {%0,%1,%2,%3};\n"
        : "+f"(c[0]), "+f"(c[1]), "+f"(c[2]), "+f"(c[3])
        : "r"(a0), "r"(a1), "r"(a2), "r"(a3), "r"(b0), "r"(b1));
}

// Tile geometry (shared by both kernels)
//   CTA tile: 128(m) x 128(n) x 16(k); 256 threads = 8 warps in a 2(m) x 4(n) grid
//   warp tile: 64(m) x 32(n) -> 4 x 4 mma.m16n8k8 tiles per k-step, 2 k-steps/tile
//   smem row stride 20 floats: bank = (20*g + c) % 32 covers all 32 banks
//   Precision: 3xTF32 split (hi = tf32(v), lo = tf32(v - hi));
//   acc += ah*bh + al*bh + ah*bl  -> error O(eps_tf32^2) ~ 1e-7 relative
#define BM 128
#define BN 128
#define BK 16
#define SROW 20

// Shared inner-loop body: loads fp32 fragments from smem, splits, 3x mma.
template <typename AccT>
__device__ __forceinline__ void mma_step_3xtf32(const float* Xs, const float* Ws,
                                                int wm, int wn, int g, int tig,
                                                AccT& acc) {
#pragma unroll
    for (int ks = 0; ks < 2; ks++) {
        const int kk = ks * 8;
        // ---- B fragments: convert once, keep hi/lo resident ----
        uint32_t bh[4][2], bl[4][2];
#pragma unroll
        for (int nt = 0; nt < 4; nt++) {
            const float* bb = &Ws[(wn * 32 + nt * 8 + g) * SROW + kk + tig];
            float f0 = bb[0], f1 = bb[4];
            bh[nt][0] = f2tf32(f0);
            bh[nt][1] = f2tf32(f1);
            bl[nt][0] = f2tf32(f0 - __uint_as_float(bh[nt][0]));
            bl[nt][1] = f2tf32(f1 - __uint_as_float(bh[nt][1]));
        }
        // ---- A fragments per-mt (limits live registers) ----
#pragma unroll
        for (int mt = 0; mt < 4; mt++) {
            const float* ab = &Xs[(wm * 64 + mt * 16 + g) * SROW + kk + tig];
            float f0 = ab[0];
            float f1 = ab[8 * SROW];
            float f2 = ab[4];
            float f3 = ab[8 * SROW + 4];
            uint32_t ah0 = f2tf32(f0), ah1 = f2tf32(f1), ah2 = f2tf32(f2), ah3 = f2tf32(f3);
            uint32_t al0 = f2tf32(f0 - __uint_as_float(ah0));
            uint32_t al1 = f2tf32(f1 - __uint_as_float(ah1));
            uint32_t al2 = f2tf32(f2 - __uint_as_float(ah2));
            uint32_t al3 = f2tf32(f3 - __uint_as_float(ah3));
#pragma unroll
            for (int nt = 0; nt < 4; nt++) {
                mma_tf32(acc[mt][nt], ah0, ah1, ah2, ah3, bh[nt][0], bh[nt][1]);
                mma_tf32(acc[mt][nt], al0, al1, al2, al3, bh[nt][0], bh[nt][1]);
                mma_tf32(acc[mt][nt], ah0, ah1, ah2, ah3, bl[nt][0], bl[nt][1]);
            }
        }
    }
}

// ---------------------------------------------------------------------------
// Kernel 1: H = (x @ A_all^T) * coef   [MTOK x NR], A_all = lora_A as [128, 4096]
// grid: (1, MTOK/128), 256 threads
// ---------------------------------------------------------------------------
__global__ __launch_bounds__(256)
void gemm_h(const float* __restrict__ X, const float* __restrict__ loraA,
            const float* __restrict__ lw) {
    __shared__ float Xs[2][BM * SROW];
    __shared__ float Ws[2][BN * SROW];

    const int tid = threadIdx.x;
    const int m0  = blockIdx.y * BM;
    const int wid = tid >> 5, lane = tid & 31;
    const int wm  = wid >> 2, wn = wid & 3;
    const int g   = lane >> 2, tig = lane & 3;

    float acc[4][4][4];
#pragma unroll
    for (int mt = 0; mt < 4; mt++)
#pragma unroll
        for (int nt = 0; nt < 4; nt++)
#pragma unroll
            for (int i = 0; i < 4; i++) acc[mt][nt][i] = 0.0f;

    const int lr = tid >> 2;          // 0..63
    const int lc = (tid & 3) * 4;     // 0,4,8,12

    auto issue = [&](int kt, int buf) {
        const float* ga = X + (size_t)m0 * D + kt * BK;
        const float* gb = loraA + kt * BK;          // 128 rows, ld = D
#pragma unroll
        for (int p = 0; p < 2; p++) {
            int r = p * 64 + lr;
            cp_async16(&Xs[buf][r * SROW + lc], ga + (size_t)r * D + lc);
            cp_async16(&Ws[buf][r * SROW + lc], gb + (size_t)r * D + lc);
        }
        cp_commit();
    };

    issue(0, 0);
    cp_wait0();
    __syncthreads();

    const int NKT = D / BK;   // 256
    for (int kt = 0; kt < NKT; kt++) {
        const int cur = kt & 1;
        if (kt + 1 < NKT) issue(kt + 1, cur ^ 1);

        mma_step_3xtf32(Xs[cur], Ws[cur], wm, wn, g, tig, acc);

        cp_wait0();
        __syncthreads();
    }

    // Epilogue: scale column block nr by LSCALE * lora_weights[nr/16], write H
#pragma unroll
    for (int mt = 0; mt < 4; mt++) {
        const int row = m0 + wm * 64 + mt * 16 + g;
#pragma unroll
        for (int nt = 0; nt < 4; nt++) {
            const int col = wn * 32 + nt * 8 + 2 * tig;   // col even; col,col+1 same adapter
            const float c = LSCALE * __ldg(&lw[col >> 4]);
            float2 v0 = make_float2(acc[mt][nt][0] * c, acc[mt][nt][1] * c);
            float2 v1 = make_float2(acc[mt][nt][2] * c, acc[mt][nt][3] * c);
            *(float2*)&g_H[(size_t)row * NR + col]       = v0;
            *(float2*)&g_H[(size_t)(row + 8) * NR + col] = v1;
        }
    }
}

// ---------------------------------------------------------------------------
// Kernel 2: out = [x | H] @ [W | B_all]^T + bias   (K = 4096 + 128 = 4224)
// grid: (D/128, MTOK/128), 256 threads
// ---------------------------------------------------------------------------
__global__ __launch_bounds__(256)
void gemm_main(const float* __restrict__ X, const float* __restrict__ W,
               const float* __restrict__ loraB, const float* __restrict__ bias,
               float* __restrict__ out) {
    __shared__ float Xs[2][BM * SROW];
    __shared__ float Ws[2][BN * SROW];

    const int tid = threadIdx.x;
    const int m0  = blockIdx.y * BM;
    const int n0  = blockIdx.x * BN;
    const int wid = tid >> 5, lane = tid & 31;
    const int wm  = wid >> 2, wn = wid & 3;
    const int g   = lane >> 2, tig = lane & 3;

    float acc[4][4][4];
#pragma unroll
    for (int mt = 0; mt < 4; mt++)
#pragma unroll
        for (int nt = 0; nt < 4; nt++)
#pragma unroll
            for (int i = 0; i < 4; i++) acc[mt][nt][i] = 0.0f;

    const int lr = tid >> 2;
    const int lc = (tid & 3) * 4;

    auto issue = [&](int kt, int buf) {
        const float* ga;
        const float* gb;
        size_t lda, ldb;
        if (kt < D / BK) {
            ga  = X + (size_t)m0 * D + kt * BK;
            lda = D;
            gb  = W + (size_t)n0 * D + kt * BK;
            ldb = D;
        } else {
            const int na = kt - D / BK;           // adapter index 0..7
            ga  = g_H + (size_t)m0 * NR + na * RANK;
            lda = NR;
            gb  = loraB + (size_t)na * (D * RANK) + (size_t)n0 * RANK;  // [o][r], ld=16
            ldb = RANK;
        }
#pragma unroll
        for (int p = 0; p < 2; p++) {
            int r = p * 64 + lr;
            cp_async16(&Xs[buf][r * SROW + lc], ga + (size_t)r * lda + lc);
            cp_async16(&Ws[buf][r * SROW + lc], gb + (size_t)r * ldb + lc);
        }
        cp_commit();
    };

    issue(0, 0);
    cp_wait0();
    __syncthreads();

    const int NKT = D / BK + NR / BK;   // 256 + 8 = 264
    for (int kt = 0; kt < NKT; kt++) {
        const int cur = kt & 1;
        if (kt + 1 < NKT) issue(kt + 1, cur ^ 1);

        mma_step_3xtf32(Xs[cur], Ws[cur], wm, wn, g, tig, acc);

        cp_wait0();
        __syncthreads();
    }

    // Epilogue: add bias, write out
#pragma unroll
    for (int mt = 0; mt < 4; mt++) {
        const int row = m0 + wm * 64 + mt * 16 + g;
#pragma unroll
        for (int nt = 0; nt < 4; nt++) {
            const int col = n0 + wn * 32 + nt * 8 + 2 * tig;
            const float b0 = __ldg(&bias[col]);
            const float b1 = __ldg(&bias[col + 1]);
            float2 v0 = make_float2(acc[mt][nt][0] + b0, acc[mt][nt][1] + b1);
            float2 v1 = make_float2(acc[mt][nt][2] + b0, acc[mt][nt][3] + b1);
            *(float2*)&out[(size_t)row * D + col]       = v0;
            *(float2*)&out[(size_t)(row + 8) * D + col] = v1;
        }
    }
}

// ---------------------------------------------------------------------------
// Launch: H first, then the fused K=4224 GEMM (same stream -> ordered)
// ---------------------------------------------------------------------------
extern "C" void kernel_launch(void* const* d_in, const int* in_sizes, int n_in,
                              void* d_out, int out_size) {
    const float* x     = (const float*)d_in[0];   // [4,2048,4096]
    const float* loraA = (const float*)d_in[1];   // [8,16,4096] == A_all [128,4096]
    const float* loraB = (const float*)d_in[2];   // [8,4096,16]
    const float* W     = (const float*)d_in[3];   // [4096,4096]
    const float* bias  = (const float*)d_in[4];   // [4096]
    const float* lw    = (const float*)d_in[5];   // [8]
    float* out = (float*)d_out;

    gemm_h<<<dim3(1, MTOK / BM), 256>>>(x, loraA, lw);
    gemm_main<<<dim3(D / BN, MTOK / BM), 256>>>(x, W, loraB, bias, out);
}

// round 4
// speedup vs baseline: 1.7827x; 1.7827x over previous
#include <cuda_runtime.h>
#include <cstdint>

// Problem constants
#define MTOK   8192          // B_*S = 4*2048 tokens
#define D      4096          // d_in = d_out
#define NADAPT 8
#define RANK   16
#define NR     128           // NADAPT*RANK, concatenated lora rank
#define LSCALE 2.0f          // ALPHA/RANK = 32/16

// Scratch: H[m][nr] = coef_n * (x @ A_all^T), 8192*128 fp32 = 4MB (static, allowed)
__device__ float g_H[MTOK * NR];

// ---------------------------------------------------------------------------
// PTX helpers
// ---------------------------------------------------------------------------
__device__ __forceinline__ void cp_async16(void* smem, const void* gmem) {
    uint32_t sa = (uint32_t)__cvta_generic_to_shared(smem);
    asm volatile("cp.async.cg.shared.global [%0], [%1], 16;\n" :: "r"(sa), "l"(gmem));
}
__device__ __forceinline__ void cp_commit() { asm volatile("cp.async.commit_group;\n"); }
__device__ __forceinline__ void cp_wait0()  { asm volatile("cp.async.wait_group 0;\n"); }

// bf16 split of two fp32 values:
//   hi = truncate-to-bf16 (top 16 bits) -> lo = v - hi is EXACT
//   lo rounded to bf16. Dropped al*bl term in 3-mma scheme is O(2^-16) relative.
// hi reg: {lo16 = hi(f0), hi16 = hi(f1)}  (f0 = smaller k index)
__device__ __forceinline__ void split2(float f0, float f1, uint32_t& hi, uint32_t& lo) {
    uint32_t u0 = __float_as_uint(f0), u1 = __float_as_uint(f1);
    asm("prmt.b32 %0, %1, %2, 0x7632;" : "=r"(hi) : "r"(u0), "r"(u1));
    float h0 = __uint_as_float(u0 & 0xffff0000u);
    float h1 = __uint_as_float(u1 & 0xffff0000u);
    float l0 = f0 - h0;
    float l1 = f1 - h1;
    // cvt.rn.bf16x2.f32 d, a, b : d.hi16 = bf16(a), d.lo16 = bf16(b)
    asm("cvt.rn.bf16x2.f32 %0, %1, %2;" : "=r"(lo) : "f"(l1), "f"(l0));
}

__device__ __forceinline__ void mma_bf16(float c[4],
                                         uint32_t a0, uint32_t a1, uint32_t a2, uint32_t a3,
                                         uint32_t b0, uint32_t b1) {
    asm volatile(
        "mma.sync.aligned.m16n8k16.row.col.f32.bf16.bf16.f32 "
        "{%0,%1,%2,%3}, {%4,%5,%6,%7}, {%8,%9}, {%0,%1,%2,%3};\n"
        : "+f"(c[0]), "+f"(c[1]), "+f"(c[2]), "+f"(c[3])
        : "r"(a0), "r"(a1), "r"(a2), "r"(a3), "r"(b0), "r"(b1));
}

// Tile geometry (shared by both kernels)
//   CTA tile: 128(m) x 128(n) x 16(k); 256 threads = 8 warps in a 2(m) x 4(n) grid
//   warp tile: 64(m) x 32(n) -> 4 x 4 mma.m16n8k16 tiles per k-tile (one k16 step)
//   smem row stride 24 floats: 64-bit fragment loads at (row*24 + 2*tig) -> pair-bank
//   index (12g+tig) mod 16 distinct within each half-warp phase: conflict-free LDS.64
//   Precision: 3xbf16 split; acc += ah*bh + al*bh + ah*bl
#define BM 128
#define BN 128
#define BK 16
#define SROW 24

// Shared inner-loop body: float2 fragment loads, bf16 split, 3x mma per (mt,nt).
template <typename AccT>
__device__ __forceinline__ void mma_step_3xbf16(const float* Xs, const float* Ws,
                                                int wm, int wn, int g, int tig,
                                                AccT& acc) {
    // ---- B fragments: convert once, keep hi/lo resident ----
    uint32_t bh[4][2], bl[4][2];
#pragma unroll
    for (int nt = 0; nt < 4; nt++) {
        const float* bb = &Ws[(wn * 32 + nt * 8 + g) * SROW + 2 * tig];
        float2 v0 = *(const float2*)bb;         // k = 2tig, 2tig+1
        float2 v1 = *(const float2*)(bb + 8);   // k = 2tig+8, 2tig+9
        split2(v0.x, v0.y, bh[nt][0], bl[nt][0]);
        split2(v1.x, v1.y, bh[nt][1], bl[nt][1]);
    }
    // ---- A fragments per-mt (limits live registers) ----
#pragma unroll
    for (int mt = 0; mt < 4; mt++) {
        const float* ar = &Xs[(wm * 64 + mt * 16 + g) * SROW + 2 * tig];
        float2 u0 = *(const float2*)ar;                  // row g,   k 2tig..+1
        float2 u1 = *(const float2*)(ar + 8 * SROW);     // row g+8, k 2tig..+1
        float2 u2 = *(const float2*)(ar + 8);            // row g,   k 2tig+8..+9
        float2 u3 = *(const float2*)(ar + 8 * SROW + 8); // row g+8, k 2tig+8..+9
        uint32_t ah[4], al[4];
        split2(u0.x, u0.y, ah[0], al[0]);
        split2(u1.x, u1.y, ah[1], al[1]);
        split2(u2.x, u2.y, ah[2], al[2]);
        split2(u3.x, u3.y, ah[3], al[3]);
#pragma unroll
        for (int nt = 0; nt < 4; nt++) {
            mma_bf16(acc[mt][nt], ah[0], ah[1], ah[2], ah[3], bh[nt][0], bh[nt][1]);
            mma_bf16(acc[mt][nt], al[0], al[1], al[2], al[3], bh[nt][0], bh[nt][1]);
            mma_bf16(acc[mt][nt], ah[0], ah[1], ah[2], ah[3], bl[nt][0], bl[nt][1]);
        }
    }
}

// ---------------------------------------------------------------------------
// Kernel 1: H = (x @ A_all^T) * coef   [MTOK x NR], A_all = lora_A as [128, 4096]
// grid: (1, MTOK/128), 256 threads
// ---------------------------------------------------------------------------
__global__ __launch_bounds__(256)
void gemm_h(const float* __restrict__ X, const float* __restrict__ loraA,
            const float* __restrict__ lw) {
    __shared__ float Xs[2][BM * SROW];
    __shared__ float Ws[2][BN * SROW];

    const int tid = threadIdx.x;
    const int m0  = blockIdx.y * BM;
    const int wid = tid >> 5, lane = tid & 31;
    const int wm  = wid >> 2, wn = wid & 3;
    const int g   = lane >> 2, tig = lane & 3;

    float acc[4][4][4];
#pragma unroll
    for (int mt = 0; mt < 4; mt++)
#pragma unroll
        for (int nt = 0; nt < 4; nt++)
#pragma unroll
            for (int i = 0; i < 4; i++) acc[mt][nt][i] = 0.0f;

    const int lr = tid >> 2;          // 0..63
    const int lc = (tid & 3) * 4;     // 0,4,8,12

    auto issue = [&](int kt, int buf) {
        const float* ga = X + (size_t)m0 * D + kt * BK;
        const float* gb = loraA + kt * BK;          // 128 rows, ld = D
#pragma unroll
        for (int p = 0; p < 2; p++) {
            int r = p * 64 + lr;
            cp_async16(&Xs[buf][r * SROW + lc], ga + (size_t)r * D + lc);
            cp_async16(&Ws[buf][r * SROW + lc], gb + (size_t)r * D + lc);
        }
        cp_commit();
    };

    issue(0, 0);
    cp_wait0();
    __syncthreads();

    const int NKT = D / BK;   // 256
    for (int kt = 0; kt < NKT; kt++) {
        const int cur = kt & 1;
        if (kt + 1 < NKT) issue(kt + 1, cur ^ 1);

        mma_step_3xbf16(Xs[cur], Ws[cur], wm, wn, g, tig, acc);

        cp_wait0();
        __syncthreads();
    }

    // Epilogue: scale column block nr by LSCALE * lora_weights[nr/16], write H
#pragma unroll
    for (int mt = 0; mt < 4; mt++) {
        const int row = m0 + wm * 64 + mt * 16 + g;
#pragma unroll
        for (int nt = 0; nt < 4; nt++) {
            const int col = wn * 32 + nt * 8 + 2 * tig;   // col even; col,col+1 same adapter
            const float c = LSCALE * __ldg(&lw[col >> 4]);
            float2 v0 = make_float2(acc[mt][nt][0] * c, acc[mt][nt][1] * c);
            float2 v1 = make_float2(acc[mt][nt][2] * c, acc[mt][nt][3] * c);
            *(float2*)&g_H[(size_t)row * NR + col]       = v0;
            *(float2*)&g_H[(size_t)(row + 8) * NR + col] = v1;
        }
    }
}

// ---------------------------------------------------------------------------
// Kernel 2: out = [x | H] @ [W | B_all]^T + bias   (K = 4096 + 128 = 4224)
// grid: (D/128, MTOK/128), 256 threads
// ---------------------------------------------------------------------------
__global__ __launch_bounds__(256)
void gemm_main(const float* __restrict__ X, const float* __restrict__ W,
               const float* __restrict__ loraB, const float* __restrict__ bias,
               float* __restrict__ out) {
    __shared__ float Xs[2][BM * SROW];
    __shared__ float Ws[2][BN * SROW];

    const int tid = threadIdx.x;
    const int m0  = blockIdx.y * BM;
    const int n0  = blockIdx.x * BN;
    const int wid = tid >> 5, lane = tid & 31;
    const int wm  = wid >> 2, wn = wid & 3;
    const int g   = lane >> 2, tig = lane & 3;

    float acc[4][4][4];
#pragma unroll
    for (int mt = 0; mt < 4; mt++)
#pragma unroll
        for (int nt = 0; nt < 4; nt++)
#pragma unroll
            for (int i = 0; i < 4; i++) acc[mt][nt][i] = 0.0f;

    const int lr = tid >> 2;
    const int lc = (tid & 3) * 4;

    auto issue = [&](int kt, int buf) {
        const float* ga;
        const float* gb;
        size_t lda, ldb;
        if (kt < D / BK) {
            ga  = X + (size_t)m0 * D + kt * BK;
            lda = D;
            gb  = W + (size_t)n0 * D + kt * BK;
            ldb = D;
        } else {
            const int na = kt - D / BK;           // adapter index 0..7
            ga  = g_H + (size_t)m0 * NR + na * RANK;
            lda = NR;
            gb  = loraB + (size_t)na * (D * RANK) + (size_t)n0 * RANK;  // [o][r], ld=16
            ldb = RANK;
        }
#pragma unroll
        for (int p = 0; p < 2; p++) {
            int r = p * 64 + lr;
            cp_async16(&Xs[buf][r * SROW + lc], ga + (size_t)r * lda + lc);
            cp_async16(&Ws[buf][r * SROW + lc], gb + (size_t)r * ldb + lc);
        }
        cp_commit();
    };

    issue(0, 0);
    cp_wait0();
    __syncthreads();

    const int NKT = D / BK + NR / BK;   // 256 + 8 = 264
    for (int kt = 0; kt < NKT; kt++) {
        const int cur = kt & 1;
        if (kt + 1 < NKT) issue(kt + 1, cur ^ 1);

        mma_step_3xbf16(Xs[cur], Ws[cur], wm, wn, g, tig, acc);

        cp_wait0();
        __syncthreads();
    }

    // Epilogue: add bias, write out
#pragma unroll
    for (int mt = 0; mt < 4; mt++) {
        const int row = m0 + wm * 64 + mt * 16 + g;
#pragma unroll
        for (int nt = 0; nt < 4; nt++) {
            const int col = n0 + wn * 32 + nt * 8 + 2 * tig;
            const float b0 = __ldg(&bias[col]);
            const float b1 = __ldg(&bias[col + 1]);
            float2 v0 = make_float2(acc[mt][nt][0] + b0, acc[mt][nt][1] + b1);
            float2 v1 = make_float2(acc[mt][nt][2] + b0, acc[mt][nt][3] + b1);
            *(float2*)&out[(size_t)row * D + col]       = v0;
            *(float2*)&out[(size_t)(row + 8) * D + col] = v1;
        }
    }
}

// ---------------------------------------------------------------------------
// Launch: H first, then the fused K=4224 GEMM (same stream -> ordered)
// ---------------------------------------------------------------------------
extern "C" void kernel_launch(void* const* d_in, const int* in_sizes, int n_in,
                              void* d_out, int out_size) {
    const float* x     = (const float*)d_in[0];   // [4,2048,4096]
    const float* loraA = (const float*)d_in[1];   // [8,16,4096] == A_all [128,4096]
    const float* loraB = (const float*)d_in[2];   // [8,4096,16]
    const float* W     = (const float*)d_in[3];   // [4096,4096]
    const float* bias  = (const float*)d_in[4];   // [4096]
    const float* lw    = (const float*)d_in[5];   // [8]
    float* out = (float*)d_out;

    gemm_h<<<dim3(1, MTOK / BM), 256>>>(x, loraA, lw);
    gemm_main<<<dim3(D / BN, MTOK / BM), 256>>>(x, W, loraB, bias, out);
}

// round 7
// speedup vs baseline: 2.1866x; 1.2266x over previous
#include <cuda_runtime.h>
#include <cuda_bf16.h>
#include <cstdint>

// ---------------------------------------------------------------------------
// Problem constants
// ---------------------------------------------------------------------------
#define MTOK   8192          // B_*S tokens
#define D      4096
#define NADAPT 8
#define RANK   16
#define NR     128           // NADAPT*RANK
#define KTOT   4224          // D + NR, concatenated GEMM K
#define LSCALE 2.0f          // ALPHA/RANK
#define KS     4             // K-split factor for gemm_h

// ---------------------------------------------------------------------------
// Global scratch (static __device__ arrays: allocation-guard-safe)
//   g_Hp : 4 K-split partials of H (coef-scaled), summed in convert_x
//   g_Xh/g_Xl : bf16 hi/lo planes of [x | H]     [MTOK][KTOT]
//   g_Bh/g_Bl : bf16 hi/lo planes of [W | B_all] [D][KTOT]
// ---------------------------------------------------------------------------
__device__ __align__(128) float          g_Hp[KS * MTOK * NR];
__device__ __align__(128) __nv_bfloat16  g_Xh[(size_t)MTOK * KTOT];
__device__ __align__(128) __nv_bfloat16  g_Xl[(size_t)MTOK * KTOT];
__device__ __align__(128) __nv_bfloat16  g_Bh[(size_t)D    * KTOT];
__device__ __align__(128) __nv_bfloat16  g_Bl[(size_t)D    * KTOT];

// ---------------------------------------------------------------------------
// Helpers
// ---------------------------------------------------------------------------
__device__ __forceinline__ void cp_async16(void* smem, const void* gmem) {
    uint32_t sa = (uint32_t)__cvta_generic_to_shared(smem);
    asm volatile("cp.async.cg.shared.global [%0], [%1], 16;\n" :: "r"(sa), "l"(gmem));
}
__device__ __forceinline__ void cp_commit() { asm volatile("cp.async.commit_group;\n"); }
__device__ __forceinline__ void cp_wait0()  { asm volatile("cp.async.wait_group 0;\n"); }

// bf16 split of two fp32 values: hi = truncate-to-bf16 (exact residual), lo = rn-bf16.
// hi packs {lo16=hi(f0), hi16=hi(f1)}; lo packs {lo16=lo(f0), hi16=lo(f1)}.
__device__ __forceinline__ void split2(float f0, float f1, uint32_t& hi, uint32_t& lo) {
    uint32_t u0 = __float_as_uint(f0), u1 = __float_as_uint(f1);
    asm("prmt.b32 %0, %1, %2, 0x7632;" : "=r"(hi) : "r"(u0), "r"(u1));
    float h0 = __uint_as_float(u0 & 0xffff0000u);
    float h1 = __uint_as_float(u1 & 0xffff0000u);
    float l0 = f0 - h0;
    float l1 = f1 - h1;
    asm("cvt.rn.bf16x2.f32 %0, %1, %2;" : "=r"(lo) : "f"(l1), "f"(l0));
}

__device__ __forceinline__ void mma_bf16(float c[4],
                                         uint32_t a0, uint32_t a1, uint32_t a2, uint32_t a3,
                                         uint32_t b0, uint32_t b1) {
    asm volatile(
        "mma.sync.aligned.m16n8k16.row.col.f32.bf16.bf16.f32 "
        "{%0,%1,%2,%3}, {%4,%5,%6,%7}, {%8,%9}, {%0,%1,%2,%3};\n"
        : "+f"(c[0]), "+f"(c[1]), "+f"(c[2]), "+f"(c[3])
        : "r"(a0), "r"(a1), "r"(a2), "r"(a3), "r"(b0), "r"(b1));
}

// ---------------------------------------------------------------------------
// Kernel 1: H partial = (x @ A_all^T) * coef over K-range [ks*1024, ks*1024+1024)
// grid (KS, 64), 256 threads; SIMT bf16 3-pass with in-loop split (fp32 inputs)
// ---------------------------------------------------------------------------
#define BM 128
#define BN 128
#define BK 16
#define SROW 24

__global__ __launch_bounds__(256)
void gemm_h(const float* __restrict__ X, const float* __restrict__ loraA,
            const float* __restrict__ lw) {
    __shared__ float Xs[2][BM * SROW];
    __shared__ float Ws[2][BN * SROW];

    const int tid = threadIdx.x;
    const int m0  = blockIdx.y * BM;
    const int ksp = blockIdx.x;                 // K-split index
    const int wid = tid >> 5, lane = tid & 31;
    const int wm  = wid >> 2, wn = wid & 3;
    const int g   = lane >> 2, tig = lane & 3;

    float acc[4][4][4];
#pragma unroll
    for (int mt = 0; mt < 4; mt++)
#pragma unroll
        for (int nt = 0; nt < 4; nt++)
#pragma unroll
            for (int i = 0; i < 4; i++) acc[mt][nt][i] = 0.0f;

    const int lr = tid >> 2;
    const int lc = (tid & 3) * 4;

    auto issue = [&](int kt, int buf) {
        const float* ga = X + (size_t)m0 * D + kt * BK;
        const float* gb = loraA + kt * BK;
#pragma unroll
        for (int p = 0; p < 2; p++) {
            int r = p * 64 + lr;
            cp_async16(&Xs[buf][r * SROW + lc], ga + (size_t)r * D + lc);
            cp_async16(&Ws[buf][r * SROW + lc], gb + (size_t)r * D + lc);
        }
        cp_commit();
    };

    const int kt0 = ksp * (D / BK / KS);        // 64 tiles per split
    const int kt1 = kt0 + (D / BK / KS);

    issue(kt0, 0);
    cp_wait0();
    __syncthreads();

    for (int kt = kt0; kt < kt1; kt++) {
        const int cur = kt & 1;
        if (kt + 1 < kt1) issue(kt + 1, cur ^ 1);

        const float* Xc = Xs[cur];
        const float* Wc = Ws[cur];
        uint32_t bh[4][2], bl[4][2];
#pragma unroll
        for (int nt = 0; nt < 4; nt++) {
            const float* bb = &Wc[(wn * 32 + nt * 8 + g) * SROW + 2 * tig];
            float2 v0 = *(const float2*)bb;
            float2 v1 = *(const float2*)(bb + 8);
            split2(v0.x, v0.y, bh[nt][0], bl[nt][0]);
            split2(v1.x, v1.y, bh[nt][1], bl[nt][1]);
        }
#pragma unroll
        for (int mt = 0; mt < 4; mt++) {
            const float* ar = &Xc[(wm * 64 + mt * 16 + g) * SROW + 2 * tig];
            float2 u0 = *(const float2*)ar;
            float2 u1 = *(const float2*)(ar + 8 * SROW);
            float2 u2 = *(const float2*)(ar + 8);
            float2 u3 = *(const float2*)(ar + 8 * SROW + 8);
            uint32_t ah[4], al[4];
            split2(u0.x, u0.y, ah[0], al[0]);
            split2(u1.x, u1.y, ah[1], al[1]);
            split2(u2.x, u2.y, ah[2], al[2]);
            split2(u3.x, u3.y, ah[3], al[3]);
#pragma unroll
            for (int nt = 0; nt < 4; nt++) {
                mma_bf16(acc[mt][nt], ah[0], ah[1], ah[2], ah[3], bh[nt][0], bh[nt][1]);
                mma_bf16(acc[mt][nt], al[0], al[1], al[2], al[3], bh[nt][0], bh[nt][1]);
                mma_bf16(acc[mt][nt], ah[0], ah[1], ah[2], ah[3], bl[nt][0], bl[nt][1]);
            }
        }
        cp_wait0();
        __syncthreads();
    }

    float* Hp = g_Hp + (size_t)ksp * MTOK * NR;
#pragma unroll
    for (int mt = 0; mt < 4; mt++) {
        const int row = m0 + wm * 64 + mt * 16 + g;
#pragma unroll
        for (int nt = 0; nt < 4; nt++) {
            const int col = wn * 32 + nt * 8 + 2 * tig;
            const float c = LSCALE * __ldg(&lw[col >> 4]);
            float2 v0 = make_float2(acc[mt][nt][0] * c, acc[mt][nt][1] * c);
            float2 v1 = make_float2(acc[mt][nt][2] * c, acc[mt][nt][3] * c);
            *(float2*)&Hp[(size_t)row * NR + col]       = v0;
            *(float2*)&Hp[(size_t)(row + 8) * NR + col] = v1;
        }
    }
}

// ---------------------------------------------------------------------------
// Kernel 2: convert [x | sum(Hp)] -> g_Xh / g_Xl (4 k-elements per thread)
// grid = MTOK*KTOT/4/256 = 33792
// ---------------------------------------------------------------------------
__global__ __launch_bounds__(256)
void convert_x(const float* __restrict__ x) {
    size_t idx = (size_t)blockIdx.x * 256 + threadIdx.x;
    size_t e   = idx * 4;
    int m = (int)(e / KTOT);
    int k = (int)(e % KTOT);
    float4 v;
    if (k < D) {
        v = *(const float4*)&x[(size_t)m * D + k];
    } else {
        size_t off = (size_t)m * NR + (k - D);
        float4 p0 = *(const float4*)&g_Hp[off];
        float4 p1 = *(const float4*)&g_Hp[(size_t)1 * MTOK * NR + off];
        float4 p2 = *(const float4*)&g_Hp[(size_t)2 * MTOK * NR + off];
        float4 p3 = *(const float4*)&g_Hp[(size_t)3 * MTOK * NR + off];
        v.x = (p0.x + p1.x) + (p2.x + p3.x);
        v.y = (p0.y + p1.y) + (p2.y + p3.y);
        v.z = (p0.z + p1.z) + (p2.z + p3.z);
        v.w = (p0.w + p1.w) + (p2.w + p3.w);
    }
    uint32_t h0, l0, h1, l1;
    split2(v.x, v.y, h0, l0);
    split2(v.z, v.w, h1, l1);
    *(uint2*)&g_Xh[(size_t)m * KTOT + k] = make_uint2(h0, h1);
    *(uint2*)&g_Xl[(size_t)m * KTOT + k] = make_uint2(l0, l1);
}

// ---------------------------------------------------------------------------
// Kernel 3: convert [W | B_all] -> g_Bh / g_Bl
// grid = D*KTOT/4/256 = 16896
// ---------------------------------------------------------------------------
__global__ __launch_bounds__(256)
void convert_b(const float* __restrict__ W, const float* __restrict__ loraB) {
    size_t idx = (size_t)blockIdx.x * 256 + threadIdx.x;
    size_t e   = idx * 4;
    int n = (int)(e / KTOT);
    int k = (int)(e % KTOT);
    float4 v;
    if (k < D) {
        v = *(const float4*)&W[(size_t)n * D + k];
    } else {
        int na = (k - D) >> 4;
        int r  = (k - D) & 15;
        v = *(const float4*)&loraB[((size_t)na * D + n) * RANK + r];
    }
    uint32_t h0, l0, h1, l1;
    split2(v.x, v.y, h0, l0);
    split2(v.z, v.w, h1, l1);
    *(uint2*)&g_Bh[(size_t)n * KTOT + k] = make_uint2(h0, h1);
    *(uint2*)&g_Bl[(size_t)n * KTOT + k] = make_uint2(l0, l1);
}

// ---------------------------------------------------------------------------
// Kernel 4: main GEMM on precomputed bf16 planes.
//   out[m][n] = AhBh + AlBh + AhBl + bias   (fp32 mma accumulators)
//   CTA tile 128x128 x BKB=32(bf16); 8 warps 2x4; warp tile 64x32.
//   smem: 4 planes (Ah,Al,Bh,Bl) x 128 rows x SRB=40 bf16, double-buffered
//   = 81920 B dynamic. Row stride 40 bf16 = 20 words: (20g + tig) mod 32
//   distinct across the 8x4 lane grid -> conflict-free LDS.32.
// ---------------------------------------------------------------------------
#define BKB   32
#define SRB   40
#define PLANE (128 * SRB)                  // bf16 units per plane tile
#define SMEM_MAIN (2 * 4 * PLANE * 2)      // bytes = 81920

__global__ __launch_bounds__(256)
void gemm_mainp(const float* __restrict__ bias, float* __restrict__ out) {
    extern __shared__ __align__(16) __nv_bfloat16 sm[];

    const int tid = threadIdx.x;
    const int m0  = blockIdx.y * BM;
    const int n0  = blockIdx.x * BN;
    const int wid = tid >> 5, lane = tid & 31;
    const int wm  = wid >> 2, wn = wid & 3;
    const int g   = lane >> 2, tig = lane & 3;

    float acc[4][4][4];
#pragma unroll
    for (int mt = 0; mt < 4; mt++)
#pragma unroll
        for (int nt = 0; nt < 4; nt++)
#pragma unroll
            for (int i = 0; i < 4; i++) acc[mt][nt][i] = 0.0f;

    const int lr  = tid >> 2;          // 0..63 row
    const int lch = (tid & 3) * 8;     // bf16 chunk offset 0,8,16,24

    const __nv_bfloat16* gXh = g_Xh + (size_t)m0 * KTOT;
    const __nv_bfloat16* gXl = g_Xl + (size_t)m0 * KTOT;
    const __nv_bfloat16* gBh = g_Bh + (size_t)n0 * KTOT;
    const __nv_bfloat16* gBl = g_Bl + (size_t)n0 * KTOT;

    auto issue = [&](int kt, int buf) {
        const size_t gk = (size_t)kt * BKB;
        __nv_bfloat16* s = sm + buf * 4 * PLANE;
#pragma unroll
        for (int p = 0; p < 2; p++) {
            const int r = p * 64 + lr;
            const size_t go = (size_t)r * KTOT + gk + lch;
            const int so = r * SRB + lch;
            cp_async16(&s[so],             gXh + go);
            cp_async16(&s[PLANE + so],     gXl + go);
            cp_async16(&s[2 * PLANE + so], gBh + go);
            cp_async16(&s[3 * PLANE + so], gBl + go);
        }
        cp_commit();
    };

    issue(0, 0);
    cp_wait0();
    __syncthreads();

    const int NKT = KTOT / BKB;   // 132
    for (int kt = 0; kt < NKT; kt++) {
        const int cur = kt & 1;
        if (kt + 1 < NKT) issue(kt + 1, cur ^ 1);

        const __nv_bfloat16* s = sm + cur * 4 * PLANE;
#pragma unroll
        for (int ks = 0; ks < 2; ks++) {
            const int kk = ks * 16;
            uint32_t bh[4][2], bl[4][2];
#pragma unroll
            for (int nt = 0; nt < 4; nt++) {
                const int base = (wn * 32 + nt * 8 + g) * SRB + kk + 2 * tig;
                bh[nt][0] = *(const uint32_t*)&s[2 * PLANE + base];
                bh[nt][1] = *(const uint32_t*)&s[2 * PLANE + base + 8];
                bl[nt][0] = *(const uint32_t*)&s[3 * PLANE + base];
                bl[nt][1] = *(const uint32_t*)&s[3 * PLANE + base + 8];
            }
#pragma unroll
            for (int mt = 0; mt < 4; mt++) {
                const int ab = (wm * 64 + mt * 16 + g) * SRB + kk + 2 * tig;
                uint32_t ah0 = *(const uint32_t*)&s[ab];
                uint32_t ah1 = *(const uint32_t*)&s[ab + 8 * SRB];
                uint32_t ah2 = *(const uint32_t*)&s[ab + 8];
                uint32_t ah3 = *(const uint32_t*)&s[ab + 8 * SRB + 8];
                uint32_t al0 = *(const uint32_t*)&s[PLANE + ab];
                uint32_t al1 = *(const uint32_t*)&s[PLANE + ab + 8 * SRB];
                uint32_t al2 = *(const uint32_t*)&s[PLANE + ab + 8];
                uint32_t al3 = *(const uint32_t*)&s[PLANE + ab + 8 * SRB + 8];
#pragma unroll
                for (int nt = 0; nt < 4; nt++) {
                    mma_bf16(acc[mt][nt], ah0, ah1, ah2, ah3, bh[nt][0], bh[nt][1]);
                    mma_bf16(acc[mt][nt], al0, al1, al2, al3, bh[nt][0], bh[nt][1]);
                    mma_bf16(acc[mt][nt], ah0, ah1, ah2, ah3, bl[nt][0], bl[nt][1]);
                }
            }
        }
        cp_wait0();
        __syncthreads();
    }

    // Epilogue: add bias, write out
#pragma unroll
    for (int mt = 0; mt < 4; mt++) {
        const int row = m0 + wm * 64 + mt * 16 + g;
#pragma unroll
        for (int nt = 0; nt < 4; nt++) {
            const int col = n0 + wn * 32 + nt * 8 + 2 * tig;
            const float b0 = __ldg(&bias[col]);
            const float b1 = __ldg(&bias[col + 1]);
            float2 v0 = make_float2(acc[mt][nt][0] + b0, acc[mt][nt][1] + b1);
            float2 v1 = make_float2(acc[mt][nt][2] + b0, acc[mt][nt][3] + b1);
            *(float2*)&out[(size_t)row * D + col]       = v0;
            *(float2*)&out[(size_t)(row + 8) * D + col] = v1;
        }
    }
}

// ---------------------------------------------------------------------------
// Launch: gemm_h (K-split) -> converts -> main plane GEMM (stream-ordered)
// ---------------------------------------------------------------------------
extern "C" void kernel_launch(void* const* d_in, const int* in_sizes, int n_in,
                              void* d_out, int out_size) {
    const float* x     = (const float*)d_in[0];   // [4,2048,4096]
    const float* loraA = (const float*)d_in[1];   // [8,16,4096]
    const float* loraB = (const float*)d_in[2];   // [8,4096,16]
    const float* W     = (const float*)d_in[3];   // [4096,4096]
    const float* bias  = (const float*)d_in[4];   // [4096]
    const float* lw    = (const float*)d_in[5];   // [8]
    float* out = (float*)d_out;

    static bool attr_set = false;
    if (!attr_set) {
        cudaFuncSetAttribute(gemm_mainp, cudaFuncAttributeMaxDynamicSharedMemorySize,
                             SMEM_MAIN);
        attr_set = true;
    }

    gemm_h   <<<dim3(KS, MTOK / BM), 256>>>(x, loraA, lw);
    convert_x<<<(int)((size_t)MTOK * KTOT / 4 / 256), 256>>>(x);
    convert_b<<<(int)((size_t)D * KTOT / 4 / 256), 256>>>(W, loraB);
    gemm_mainp<<<dim3(D / BN, MTOK / BM), 256, SMEM_MAIN>>>(bias, out);
}